// round 14
// baseline (speedup 1.0000x reference)
#include <cuda_runtime.h>
#include <math.h>
#include <math_constants.h>

#define H 128
#define HP 129
#define NSEG 129
#define NPIECE 129
#define THRESH 0.045f
#define INV_TAU 0.05f
#define THR 1024
#define NWARP 32
#define NCMAX (NSEG * H + NSEG - 1)     // 16640
#define NPMAX (NCMAX + 1)               // 16641
#define NB 8192
#define XLO (-8.0f)
#define BINSCALE 512.0f
#define BT 512

// smem layout for k_main (bytes) — every region 16B-aligned
#define CUT_FLOATS (NCMAX + 12)              // 16652 floats; 66608 B (16-aligned)
#define OFF_AB   (CUT_FLOATS * 4)            // 66608
#define AB_BYTES (16642 * 8)                 // 133136 B (16-aligned; holds NPMAX=16641)
#define OFF_BIN  (OFF_AB + AB_BYTES)         // 199744 (16-aligned)
#define BIN_BYTES (1025 * 16)                // 16400 B >= 8193 shorts
#define SMEM_MAIN (OFF_BIN + BIN_BYTES)

// -------- device scratch (no cudaMalloc) --------
__device__ float  g_bp[H];
__device__ float  g_cut[NSEG * H];
__device__ float2 g_AB[NSEG * NPIECE];
__device__ int    g_cnt[NSEG];
__device__ __align__(16) float  g_cutC[NCMAX];
__device__ __align__(16) float2 g_ABC[NPMAX + 1];
__device__ __align__(16) unsigned short g_bin[NB + 8];   // 8200 shorts = 16400 B
__device__ int    g_meta[4];
__device__ unsigned long long g_sync[256];
__device__ int    g_df[NSEG];            // per-segment done flags (reset by setup)

// ========= Kernel A: build blocks 0..128 + setup block 129 =========
__global__ void __launch_bounds__(THR, 1)
k_build(const float* __restrict__ W1, const float* __restrict__ B1,
        const float* __restrict__ W2, const float* __restrict__ B2,
        const float* __restrict__ W3, const float* __restrict__ B3) {
    extern __shared__ float dynf[];
    int s = blockIdx.x, t = threadIdx.x;
    int lane = t & 31, w = t >> 5;

    // ===================== SETUP BLOCK (bid NSEG) =====================
    if (s == NSEG) {
        __shared__ int soff[NSEG + 1];
        __shared__ int sNC;
        __shared__ int swsum[NWARP];
        int* cnt8 = (int*)dynf;                   // NB ints
        for (int i = t; i < NB; i += THR) cnt8[i] = 0;
        // wait for all build blocks, reset flags for next replay
        for (int i = t; i < NSEG; i += THR) {
            volatile int* p = g_df + i;
            while (*p == 0) { }
            *p = 0;
        }
        __syncthreads();
        __threadfence();
        if (t == 0) {
            int o = 0;
            #pragma unroll 4
            for (int u = 0; u < NSEG; u++) { soff[u] = o; o += g_cnt[u] + 1; }
            soff[NSEG] = o;
            sNC = o - 1;
            g_meta[0] = o - 1;
        }
        __syncthreads();
        int NC = sNC, NP = NC + 1;
        for (int p = t; p < NP; p += THR) {
            int lo = 0, hi = NSEG;
            while (lo + 1 < hi) {
                int mid = (lo + hi) >> 1;
                if (soff[mid] <= p) lo = mid; else hi = mid;
            }
            int u = lo;
            int k = p - soff[u];
            int cnt = soff[u + 1] - soff[u] - 1;
            g_ABC[p] = g_AB[u * NPIECE + k];
            if (p < NC) {
                float cv = (k < cnt) ? g_cut[u * H + k] : g_bp[u];
                g_cutC[p] = cv;
                int bin = (int)((cv - XLO) * BINSCALE);
                bin = min(max(bin, 0), NB - 1);
                atomicAdd(&cnt8[bin], 1);
            }
        }
        __syncthreads();
        const int PER = NB / THR;   // 8
        int base = t * PER;
        int loc[PER];
        int tsum = 0;
        #pragma unroll
        for (int i = 0; i < PER; i++) { loc[i] = cnt8[base + i]; tsum += loc[i]; }
        int inc = tsum;
        #pragma unroll
        for (int o = 1; o < 32; o <<= 1) {
            int u = __shfl_up_sync(0xffffffffu, inc, o);
            if (lane >= o) inc += u;
        }
        if (lane == 31) swsum[w] = inc;
        __syncthreads();
        if (w == 0) {
            int z = swsum[lane];
            #pragma unroll
            for (int o = 1; o < 32; o <<= 1) {
                int u = __shfl_up_sync(0xffffffffu, z, o);
                if (lane >= o) z += u;
            }
            swsum[lane] = z;
        }
        __syncthreads();
        int excl = inc - tsum + ((w > 0) ? swsum[w - 1] : 0);
        #pragma unroll
        for (int i = 0; i < PER; i++) {
            g_bin[base + i] = (unsigned short)excl;
            excl += loc[i];
        }
        if (t == THR - 1) {
            g_bin[NB] = (unsigned short)excl;
            #pragma unroll
            for (int i = 1; i < 8; i++) g_bin[NB + i] = (unsigned short)excl;
        }
        return;
    }

    // ===================== BUILD BLOCKS (R10 body @512 active thr) ==========
    {
        float* sW2 = dynf;                           // H * HP padded
        __shared__ float sw1[H], sb1[H], sbp[H], sbpS[H];
        __shared__ float swm[H], sbm[H];
        __shared__ float skey[H], sdA[H], sdB[H];
        __shared__ float pA[4][H], pB[4][H];
        __shared__ float pSA[4][H], pSB[4][H];
        __shared__ int   pPre[4][H];
        __shared__ float redA[4], redB[4];
        __shared__ int   scw[4];
        int j = t & 127, q = (t >> 7) & 3;
        bool act512 = (t < BT);

        if (s == 0) {
            if (t < 256) g_sync[t] = 0ull;
        }

        const float4* w4 = (const float4*)W2;
        #pragma unroll
        for (int i = t; i < (H * H) / 4; i += THR) {
            float4 v = w4[i];
            int base = i << 2;
            int row = base >> 7, col = base & 127;
            float* dst = sW2 + row * HP + col;
            dst[0] = v.x; dst[1] = v.y; dst[2] = v.z; dst[3] = v.w;
        }
        if (act512 && q == 0) {
            float wj = W1[j], bj = B1[j];
            sw1[j] = wj; sb1[j] = bj;
            sbp[j] = (wj == 0.0f) ? CUDART_INF_F : (-bj / wj);
        }
        __syncthreads();

        float bpj = sbp[j];
        if (act512) {
            int r = 0;
            #pragma unroll 8
            for (int k = q * 32; k < q * 32 + 32; k++) {
                float v = sbp[k];
                r += (v < bpj) || (v == bpj && k < j);
            }
            pPre[q][j] = r;
        }
        __syncthreads();
        if (act512 && q == 0) {
            int rank = pPre[0][j] + pPre[1][j] + pPre[2][j] + pPre[3][j];
            sbpS[rank] = bpj;
            if (s == 0) g_bp[rank] = bpj;
        }
        __syncthreads();
        float L = (s == 0)        ? -CUDART_INF_F : sbpS[s - 1];
        float R = (s == NSEG - 1) ?  CUDART_INF_F : sbpS[s];
        if (act512 && q == 0) {
            float wj = sw1[j], bj = sb1[j];
            bool act;
            if (wj > 0.0f)      act = (bpj <= L);
            else if (wj < 0.0f) act = (bpj >= R);
            else                act = (bj > 0.0f);
            swm[j] = act ? wj : 0.0f;
            sbm[j] = act ? bj : 0.0f;
        }
        __syncthreads();

        if (act512) {
            float a = 0.0f, be = 0.0f;
            const float* row = sW2 + j * HP;
            #pragma unroll 8
            for (int m = q * 32; m < q * 32 + 32; m++) {
                float c = row[m];
                a  = fmaf(c, swm[m], a);
                be = fmaf(c, sbm[m], be);
            }
            pA[q][j] = a; pB[q][j] = be;
        }
        __syncthreads();

        if (act512 && q == 0) {
            float a  = pA[0][j] + pA[1][j] + pA[2][j] + pA[3][j];
            float be = pB[0][j] + pB[1][j] + pB[2][j] + pB[3][j] + __ldg(&B2[j]);
            float w3 = __ldg(&W3[j]);
            float c = -be / a;
            bool hasbp = (a != 0.0f) && (c > L) && (c < R);
            bool actL;
            if (a > 0.0f)      actL = (c <= L);
            else if (a < 0.0f) actL = (c > L);
            else               actL = (be > 0.0f);
            float eA = actL ? w3 * a  : 0.0f;
            float eB = actL ? w3 * be : 0.0f;
            float sgn = (a > 0.0f) ? 1.0f : -1.0f;
            skey[j] = hasbp ? c : CUDART_INF_F;
            sdA[j]  = hasbp ? sgn * w3 * a  : 0.0f;
            sdB[j]  = hasbp ? sgn * w3 * be : 0.0f;
            #pragma unroll
            for (int o = 16; o; o >>= 1) {
                eA += __shfl_xor_sync(0xffffffffu, eA, o);
                eB += __shfl_xor_sync(0xffffffffu, eB, o);
            }
            unsigned bal = __ballot_sync(0xffffffffu, hasbp);
            if (lane == 0) { redA[w] = eA; redB[w] = eB; scw[w] = __popc(bal); }
        }
        __syncthreads();
        if (t == 0) g_cnt[s] = scw[0] + scw[1] + scw[2] + scw[3];

        if (act512) {
            float key = skey[j];
            int pre = 0;
            float sA = 0.0f, sB = 0.0f;
            #pragma unroll 8
            for (int k = q * 32; k < q * 32 + 32; k++) {
                float kk = skey[k];
                bool p = (kk < key) || (kk == key && k <= j);
                if (p) { sA += sdA[k]; sB += sdB[k]; pre++; }
            }
            pPre[q][j] = pre; pSA[q][j] = sA; pSB[q][j] = sB;
        }
        __syncthreads();
        if (act512 && q == 0) {
            float A0 = redA[0] + redA[1] + redA[2] + redA[3];
            float B0 = redB[0] + redB[1] + redB[2] + redB[3] + __ldg(&B3[0]);
            int pre = pPre[0][j] + pPre[1][j] + pPre[2][j] + pPre[3][j];
            float sA = pSA[0][j] + pSA[1][j] + pSA[2][j] + pSA[3][j];
            float sB = pSB[0][j] + pSB[1][j] + pSB[2][j] + pSB[3][j];
            int rank = pre - 1;
            g_cut[s * H + rank] = skey[j];
            g_AB[s * NPIECE + 1 + rank] = make_float2(A0 + sA, B0 + sB);
            if (j == 0) g_AB[s * NPIECE] = make_float2(A0, B0);
        }
        __threadfence();
        __syncthreads();
        if (t == 0) atomicExch(&g_df[s], 1);
    }
}

// ====== Kernel B: async table load overlapped with scan; fast eval =========
template <int IT>
__global__ void __launch_bounds__(THR, 1)
k_main(const float* __restrict__ x, float* __restrict__ out, int N, int out_size) {
    extern __shared__ char dyn[];
    float*  scut = (float*)dyn;
    float2* sAB  = (float2*)(dyn + OFF_AB);
    unsigned short* sbin = (unsigned short*)(dyn + OFF_BIN);
    __shared__ int stot[NWARP * 16];
    __shared__ int swarp[NWARP];
    __shared__ unsigned ssum[NWARP];
    __shared__ int sBlockLast, sSeedSh, sCntOwn;

    int t = threadIdx.x, b = blockIdx.x;
    int lane = t & 31, w = t >> 5;
    long blockBase = (long)b * THR * IT;

    // ---- phase 0: fire-and-forget async table copy (LDGSTS, all 16B) ----
    {
        unsigned cut_s = (unsigned)__cvta_generic_to_shared(scut);
        unsigned ab_s  = (unsigned)__cvta_generic_to_shared(sAB);
        unsigned bin_s = (unsigned)__cvta_generic_to_shared(sbin);
        const char* cut_g = (const char*)g_cutC;
        const char* ab_g  = (const char*)g_ABC;
        const char* bin_g = (const char*)g_bin;
        #pragma unroll 1
        for (int i = t; i < NCMAX / 4; i += THR)               // 4160 chunks
            asm volatile("cp.async.cg.shared.global [%0], [%1], 16;"
                         :: "r"(cut_s + i * 16), "l"(cut_g + i * 16));
        #pragma unroll 1
        for (int i = t; i < ((NPMAX + 1) * 8) / 16; i += THR)  // 8321 chunks (g_ABC has +1 pad)
            asm volatile("cp.async.cg.shared.global [%0], [%1], 16;"
                         :: "r"(ab_s + i * 16), "l"(ab_g + i * 16));
        #pragma unroll 1
        for (int i = t; i < BIN_BYTES / 16; i += THR)          // 1025 chunks
            asm volatile("cp.async.cg.shared.global [%0], [%1], 16;"
                         :: "r"(bin_s + i * 16), "l"(bin_g + i * 16));
        asm volatile("cp.async.commit_group;");
    }

    // ---- phase A: scan (hoisted x loads, ballot cummax) ----
    float xr[IT];
    int   vloc[IT];
    int   rr[IT];
    int cntLoc = 0;
    #pragma unroll
    for (int tile = 0; tile < IT; tile++) {
        long row = blockBase + (long)tile * THR + t;
        xr[tile] = (row < N) ? __ldg(x + row) : 0.0f;
    }
    #pragma unroll
    for (int tile = 0; tile < IT; tile++) {
        long row = blockBase + (long)tile * THR + t;
        bool valid = row < N;
        float cur = xr[tile];
        float pv = __shfl_up_sync(0xffffffffu, cur, 1);
        if (lane == 0) pv = (valid && row > 0) ? __ldg(x + row - 1) : cur;
        bool m = valid && ((row == 0) || fabsf(cur - pv) > THRESH);
        unsigned bits = __ballot_sync(0xffffffffu, m);
        cntLoc += m ? 1 : 0;
        int warpBase = (int)row - lane;
        unsigned below = bits & (0xffffffffu >> (31 - lane));
        vloc[tile] = below ? (warpBase + 31 - __clz(below)) : -1;
        if (lane == 31) stot[tile * NWARP + w] = bits ? (warpBase + 31 - __clz(bits)) : -1;
    }
    __syncthreads();
    if (w == 0) {
        int vals[IT];
        int running = -1;
        #pragma unroll
        for (int i = 0; i < IT; i++) {
            int u = stot[lane * IT + i];
            vals[i] = running;
            running = max(running, u);
        }
        int inc = running;
        #pragma unroll
        for (int o = 1; o < 32; o <<= 1) {
            int u = __shfl_up_sync(0xffffffffu, inc, o);
            if (lane >= o) inc = max(inc, u);
        }
        int exc = __shfl_up_sync(0xffffffffu, inc, 1);
        if (lane == 0) exc = -1;
        #pragma unroll
        for (int i = 0; i < IT; i++) stot[lane * IT + i] = max(vals[i], exc);
        if (lane == 31) sBlockLast = inc;
    }
    __syncthreads();
    #pragma unroll
    for (int tile = 0; tile < IT; tile++)
        rr[tile] = max(vloc[tile], stot[tile * NWARP + w]);
    int carry = sBlockLast;

    // ---- publish packet ----
    {
        int c = cntLoc;
        #pragma unroll
        for (int o = 16; o; o >>= 1) c += __shfl_xor_sync(0xffffffffu, c, o);
        if (lane == 0) swarp[w] = c;
        __syncthreads();
        if (t == 0) {
            int s = 0;
            #pragma unroll
            for (int i = 0; i < NWARP; i++) s += swarp[i];
            sCntOwn = s;
            unsigned long long pack =
                ((unsigned long long)(unsigned)(carry + 2) << 32) | (unsigned)s;
            atomicExch(&g_sync[b], pack);
        }
        __syncthreads();
    }

    // ---- decoupled lookback (seed + n_active) ----
    {
        int lastMax = -1;
        unsigned sumU = 0;
        for (int i = t; i < b; i += THR) {
            volatile unsigned long long* p = (volatile unsigned long long*)(g_sync + i);
            unsigned long long v;
            do { v = *p; } while (v == 0ull);
            lastMax = max(lastMax, (int)(unsigned)(v >> 32) - 2);
            sumU += (unsigned)(v & 0xffffffffull);
        }
        #pragma unroll
        for (int o = 16; o; o >>= 1) {
            lastMax = max(lastMax, __shfl_xor_sync(0xffffffffu, lastMax, o));
            sumU += __shfl_xor_sync(0xffffffffu, sumU, o);
        }
        if (lane == 0) { swarp[w] = lastMax; ssum[w] = sumU; }
        __syncthreads();
        if (t == 0) {
            int mx = -1; unsigned s2 = 0;
            #pragma unroll
            for (int i = 0; i < NWARP; i++) { mx = max(mx, swarp[i]); s2 += ssum[i]; }
            sSeedSh = mx;
            if (b == gridDim.x - 1 && out_size > N)
                out[N] = (float)(s2 + (unsigned)sCntOwn);
        }
        if (b == 0)
            for (int i = N + 1 + t; i < out_size; i += THR) out[i] = 0.0f;
    }

    // ---- wait for table copy, INF-pad cuts ----
    asm volatile("cp.async.wait_group 0;");
    __syncthreads();
    int NC = g_meta[0];
    if (t < 12) scut[NC + t] = CUDART_INF_F;
    __syncthreads();
    int seed = sSeedSh;

    // ---- eval: bin -> window -> vector count (independent LDS.128) ----
    const float4* scut4 = (const float4*)scut;
    #pragma unroll
    for (int tile = 0; tile < IT; tile++) {
        long row = blockBase + (long)tile * THR + t;
        if (row >= N) break;
        int irow = (int)row;
        int run = max(rr[tile], seed);
        bool own = (run == irow);
        float xv = own ? xr[tile] : __ldg(x + run);
        int bin = (int)((xv - XLO) * BINSCALE);
        bin = min(max(bin, 0), NB - 1);
        int lo = sbin[bin], hi = sbin[bin + 1];
        int piece;
        int qb = lo >> 2;
        int i0 = qb << 2;
        if (hi <= i0 + 12) {
            float4 c0 = scut4[qb];
            float4 c1 = scut4[qb + 1];
            float4 c2 = scut4[qb + 2];
            float vv[12] = {c0.x, c0.y, c0.z, c0.w, c1.x, c1.y, c1.z, c1.w,
                            c2.x, c2.y, c2.z, c2.w};
            int cnt = 0;
            #pragma unroll
            for (int k = 0; k < 12; k++) {
                int idx = i0 + k;
                cnt += (idx >= lo && idx < hi && vv[k] < xv) ? 1 : 0;
            }
            piece = lo + cnt;
        } else {
            while (lo < hi) {
                int mid = (lo + hi) >> 1;
                if (scut[mid] < xv) lo = mid + 1; else hi = mid;
            }
            piece = lo;
        }
        float2 ab = sAB[piece];
        float y = fmaf(ab.x, xv, ab.y);
        if (!own) y *= __expf((float)(run - irow) * INV_TAU);
        out[row] = y;
    }
}

#define LAUNCH_MAIN(ITV)                                                        \
    do {                                                                        \
        cudaFuncSetAttribute(k_main<ITV>,                                       \
            cudaFuncAttributeMaxDynamicSharedMemorySize, (int)SMEM_MAIN);       \
        k_main<ITV><<<grid1, THR, SMEM_MAIN>>>(x, out, N, out_size);            \
    } while (0)

extern "C" void kernel_launch(void* const* d_in, const int* in_sizes, int n_in,
                              void* d_out, int out_size) {
    const float* x  = (const float*)d_in[0];
    const float* W1 = (const float*)d_in[1];
    const float* b1 = (const float*)d_in[2];
    const float* W2 = (const float*)d_in[3];
    const float* b2 = (const float*)d_in[4];
    const float* W3 = (const float*)d_in[5];
    const float* b3 = (const float*)d_in[6];
    float* out = (float*)d_out;
    int N = in_sizes[0];

    size_t smemA = (size_t)H * HP * sizeof(float);   // 66KB, also covers setup's 32KB
    cudaFuncSetAttribute(k_build, cudaFuncAttributeMaxDynamicSharedMemorySize, (int)smemA);
    k_build<<<NSEG + 1, THR, smemA>>>(W1, b1, W2, b2, W3, b3);

    const int SMS = 147;
    long total = N;
    int IT = (int)((total + (long)SMS * THR - 1) / ((long)SMS * THR));
    if (IT < 1) IT = 1;
    if (IT > 16) IT = 16;
    int grid1 = (int)((total + (long)THR * IT - 1) / ((long)THR * IT));
    if (grid1 < 1) grid1 = 1;

    switch (IT) {
        case 1:  LAUNCH_MAIN(1);  break;
        case 2:  LAUNCH_MAIN(2);  break;
        case 3:  LAUNCH_MAIN(3);  break;
        case 4:  LAUNCH_MAIN(4);  break;
        case 5:  LAUNCH_MAIN(5);  break;
        case 6:  LAUNCH_MAIN(6);  break;
        case 7:  LAUNCH_MAIN(7);  break;
        case 8:  LAUNCH_MAIN(8);  break;
        case 9:  LAUNCH_MAIN(9);  break;
        case 10: LAUNCH_MAIN(10); break;
        case 11: LAUNCH_MAIN(11); break;
        case 12: LAUNCH_MAIN(12); break;
        case 13: LAUNCH_MAIN(13); break;
        case 14: LAUNCH_MAIN(14); break;
        case 15: LAUNCH_MAIN(15); break;
        default: LAUNCH_MAIN(16); break;
    }
}

// round 15
// speedup vs baseline: 1.2570x; 1.2570x over previous
#include <cuda_runtime.h>
#include <math.h>
#include <math_constants.h>

#define H 128
#define HP 129
#define NSEG 129
#define NPIECE 129
#define THRESH 0.045f
#define INV_TAU 0.05f
#define THR 1024
#define NWARP 32
#define NCMAX (NSEG * H + NSEG - 1)     // 16640
#define NPMAX (NCMAX + 1)               // 16641
#define NB 8192
#define XLO (-8.0f)
#define BINSCALE 512.0f
#define BT 512

// smem layout for k_main (bytes) — every region 16B-aligned
#define CUT_FLOATS (NCMAX + 12)              // 16652 floats; 66608 B
#define OFF_AB   (CUT_FLOATS * 4)            // 66608
#define AB_BYTES (16642 * 8)                 // 133136 B (holds NPMAX=16641 + pad)
#define OFF_BIN  (OFF_AB + AB_BYTES)         // 199744 (16-aligned)
#define BIN_BYTES (1025 * 16)                // 16400 B >= 8193 shorts
#define SMEM_MAIN (OFF_BIN + BIN_BYTES)

// -------- device scratch (no cudaMalloc; zero-initialized at load) --------
__device__ __align__(16) float  g_cutC[NCMAX];
__device__ __align__(16) float2 g_ABC[NPMAX + 1];
__device__ __align__(16) unsigned short g_bin[NB + 8];   // 8200 shorts = 16400 B
__device__ int    g_meta[4];                 // [0] = NC
__device__ unsigned long long g_sync[256];   // scanner lookback slots
__device__ unsigned g_bsync[NSEG];           // build lookback: cnt+1 (re-zeroed by setup)
__device__ volatile unsigned g_flag;         // bins-ready flag

// ========= Kernel A: build + direct compaction (129 blocks x 512 thr) ======
__global__ void __launch_bounds__(BT, 1)
k_build(const float* __restrict__ W1, const float* __restrict__ B1,
        const float* __restrict__ W2, const float* __restrict__ B2,
        const float* __restrict__ W3, const float* __restrict__ B3) {
    extern __shared__ float sW2[];                 // H * HP padded
    __shared__ float sw1[H], sb1[H], sbp[H], sbpS[H];
    __shared__ float swm[H], sbm[H];
    __shared__ float skey[H], sdA[H], sdB[H];
    __shared__ float pA[4][H], pB[4][H];
    __shared__ float pSA[4][H], pSB[4][H];
    __shared__ int   pPre[4][H];
    __shared__ float redA[4], redB[4];
    __shared__ int   scw[4];
    __shared__ unsigned slk[16];
    __shared__ int   sOff;
    int s = blockIdx.x, t = threadIdx.x;
    int j = t & 127, q = t >> 7;
    int lane = t & 31, w = t >> 5;

    if (s == 0) {   // zero scanner lookback slots + bins flag for kernel B
        if (t < 256) g_sync[t] = 0ull;
        if (t == 0) g_flag = 0u;
    }

    // coalesced W2 -> padded smem
    const float4* w4 = (const float4*)W2;
    #pragma unroll
    for (int i = t; i < (H * H) / 4; i += BT) {
        float4 v = w4[i];
        int base = i << 2;
        int row = base >> 7, col = base & 127;
        float* dst = sW2 + row * HP + col;
        dst[0] = v.x; dst[1] = v.y; dst[2] = v.z; dst[3] = v.w;
    }
    if (q == 0) {
        float wj = W1[j], bj = B1[j];
        sw1[j] = wj; sb1[j] = bj;
        sbp[j] = (wj == 0.0f) ? CUDART_INF_F : (-bj / wj);
    }
    __syncthreads();

    // breakpoint rank, 4-way split
    float bpj = sbp[j];
    {
        int r = 0;
        #pragma unroll 8
        for (int k = q * 32; k < q * 32 + 32; k++) {
            float v = sbp[k];
            r += (v < bpj) || (v == bpj && k < j);
        }
        pPre[q][j] = r;
    }
    __syncthreads();
    if (q == 0) {
        int rank = pPre[0][j] + pPre[1][j] + pPre[2][j] + pPre[3][j];
        sbpS[rank] = bpj;
    }
    __syncthreads();
    float L = (s == 0)        ? -CUDART_INF_F : sbpS[s - 1];
    float R = (s == NSEG - 1) ?  CUDART_INF_F : sbpS[s];
    if (q == 0) {
        float wj = sw1[j], bj = sb1[j];
        bool act;
        if (wj > 0.0f)      act = (bpj <= L);
        else if (wj < 0.0f) act = (bpj >= R);
        else                act = (bj > 0.0f);
        swm[j] = act ? wj : 0.0f;
        sbm[j] = act ? bj : 0.0f;
    }
    __syncthreads();

    // matvec partials, 4-way split over m
    {
        float a = 0.0f, be = 0.0f;
        const float* row = sW2 + j * HP;
        #pragma unroll 8
        for (int m = q * 32; m < q * 32 + 32; m++) {
            float c = row[m];
            a  = fmaf(c, swm[m], a);
            be = fmaf(c, sbm[m], be);
        }
        pA[q][j] = a; pB[q][j] = be;
    }
    __syncthreads();

    if (q == 0) {
        float a  = pA[0][j] + pA[1][j] + pA[2][j] + pA[3][j];
        float be = pB[0][j] + pB[1][j] + pB[2][j] + pB[3][j] + __ldg(&B2[j]);
        float w3 = __ldg(&W3[j]);
        float c = -be / a;
        bool hasbp = (a != 0.0f) && (c > L) && (c < R);
        bool actL;
        if (a > 0.0f)      actL = (c <= L);
        else if (a < 0.0f) actL = (c > L);
        else               actL = (be > 0.0f);
        float eA = actL ? w3 * a  : 0.0f;
        float eB = actL ? w3 * be : 0.0f;
        float sgn = (a > 0.0f) ? 1.0f : -1.0f;
        skey[j] = hasbp ? c : CUDART_INF_F;
        sdA[j]  = hasbp ? sgn * w3 * a  : 0.0f;
        sdB[j]  = hasbp ? sgn * w3 * be : 0.0f;
        #pragma unroll
        for (int o = 16; o; o >>= 1) {
            eA += __shfl_xor_sync(0xffffffffu, eA, o);
            eB += __shfl_xor_sync(0xffffffffu, eB, o);
        }
        unsigned bal = __ballot_sync(0xffffffffu, hasbp);
        if (lane == 0) { redA[w] = eA; redB[w] = eB; scw[w] = __popc(bal); }
    }
    __syncthreads();
    int cntAll = scw[0] + scw[1] + scw[2] + scw[3];
    // publish cnt+1 for successors' lookback
    if (t == 0) atomicExch(&g_bsync[s], (unsigned)(cntAll + 1));

    // decoupled lookback: offset = sum_{u<s} (cnt[u]+1)
    {
        unsigned sum = 0;
        for (int i = t; i < s; i += BT) {
            volatile unsigned* p = g_bsync + i;
            unsigned v;
            do { v = *p; } while (v == 0u);
            sum += v;
        }
        #pragma unroll
        for (int o = 16; o; o >>= 1) sum += __shfl_xor_sync(0xffffffffu, sum, o);
        if (lane == 0) slk[w] = sum;
        __syncthreads();
        if (t == 0) {
            unsigned tot = 0;
            #pragma unroll
            for (int i = 0; i < 16; i++) tot += slk[i];
            sOff = (int)tot;
        }
        __syncthreads();
    }
    int off = sOff;

    // fused rank + prefix over sorted cuts, 4-way split
    {
        float key = skey[j];
        int pre = 0;
        float sA = 0.0f, sB = 0.0f;
        #pragma unroll 8
        for (int k = q * 32; k < q * 32 + 32; k++) {
            float kk = skey[k];
            bool p = (kk < key) || (kk == key && k <= j);
            if (p) { sA += sdA[k]; sB += sdB[k]; pre++; }
        }
        pPre[q][j] = pre; pSA[q][j] = sA; pSB[q][j] = sB;
    }
    __syncthreads();
    if (q == 0) {
        float A0 = redA[0] + redA[1] + redA[2] + redA[3];
        float B0 = redB[0] + redB[1] + redB[2] + redB[3] + __ldg(&B3[0]);
        int pre = pPre[0][j] + pPre[1][j] + pPre[2][j] + pPre[3][j];
        float sA = pSA[0][j] + pSA[1][j] + pSA[2][j] + pSA[3][j];
        float sB = pSB[0][j] + pSB[1][j] + pSB[2][j] + pSB[3][j];
        int rank = pre - 1;
        if (rank < cntAll) {                       // finite cuts only
            g_cutC[off + rank] = skey[j];
            g_ABC[off + 1 + rank] = make_float2(A0 + sA, B0 + sB);
        }
        if (j == 0) g_ABC[off] = make_float2(A0, B0);
    }
    if (t == 0) {
        if (s < NSEG - 1) g_cutC[off + cntAll] = R;   // segment boundary cut
        else              g_meta[0] = off + cntAll;   // NC
    }
}

// ====== Kernel B: cp.async prefetch + scan + bins setup block + eval =======
template <int IT>
__global__ void __launch_bounds__(THR, 1)
k_main(const float* __restrict__ x, float* __restrict__ out, int N, int out_size) {
    extern __shared__ char dyn[];
    float*  scut = (float*)dyn;
    float2* sAB  = (float2*)(dyn + OFF_AB);
    unsigned short* sbin = (unsigned short*)(dyn + OFF_BIN);
    __shared__ int stot[NWARP * 16];
    __shared__ int swarp[NWARP];
    __shared__ unsigned ssum[NWARP];
    __shared__ int sBlockLast, sSeedSh, sCntOwn;

    int t = threadIdx.x, b = blockIdx.x;
    int lane = t & 31, w = t >> 5;
    int SCANB = gridDim.x - 1;

    // ===================== SETUP BLOCK (bins only) =====================
    if (b == SCANB) {
        int* cnt8 = (int*)dyn;                  // NB ints
        int NC = g_meta[0];                     // ready (kernel boundary)
        for (int i = t; i < NB; i += THR) cnt8[i] = 0;
        __syncthreads();
        for (int i = t; i < NC; i += THR) {
            float cv = g_cutC[i];
            int bin = (int)((cv - XLO) * BINSCALE);
            bin = min(max(bin, 0), NB - 1);
            atomicAdd(&cnt8[bin], 1);
        }
        __syncthreads();
        const int PER = NB / THR;   // 8
        int base = t * PER;
        int loc[PER];
        int tsum = 0;
        #pragma unroll
        for (int i = 0; i < PER; i++) { loc[i] = cnt8[base + i]; tsum += loc[i]; }
        int inc = tsum;
        #pragma unroll
        for (int o = 1; o < 32; o <<= 1) {
            int u = __shfl_up_sync(0xffffffffu, inc, o);
            if (lane >= o) inc += u;
        }
        if (lane == 31) swarp[w] = inc;
        __syncthreads();
        if (w == 0) {
            int z = swarp[lane];
            #pragma unroll
            for (int o = 1; o < 32; o <<= 1) {
                int u = __shfl_up_sync(0xffffffffu, z, o);
                if (lane >= o) z += u;
            }
            swarp[lane] = z;
        }
        __syncthreads();
        int excl = inc - tsum + ((w > 0) ? swarp[w - 1] : 0);
        #pragma unroll
        for (int i = 0; i < PER; i++) {
            g_bin[base + i] = (unsigned short)excl;
            excl += loc[i];
        }
        if (t == THR - 1) {
            #pragma unroll
            for (int i = 0; i < 8; i++) g_bin[NB + i] = (unsigned short)excl;
        }
        __threadfence();
        __syncthreads();
        if (t == 0) g_flag = 1u;

        // re-zero build lookback slots for next graph replay
        for (int i = t; i < NSEG; i += THR) g_bsync[i] = 0u;

        // n_active: sum all scanner packets
        unsigned sumU = 0;
        for (int i = t; i < SCANB; i += THR) {
            volatile unsigned long long* p = (volatile unsigned long long*)(g_sync + i);
            unsigned long long v;
            do { v = *p; } while (v == 0ull);
            sumU += (unsigned)(v & 0xffffffffull);
        }
        #pragma unroll
        for (int o = 16; o; o >>= 1) sumU += __shfl_xor_sync(0xffffffffu, sumU, o);
        if (lane == 0) ssum[w] = sumU;
        __syncthreads();
        if (t == 0 && out_size > N) {
            unsigned s2 = 0;
            #pragma unroll
            for (int i = 0; i < NWARP; i++) s2 += ssum[i];
            out[N] = (float)s2;
        }
        return;
    }

    // ===================== SCANNER BLOCKS =====================
    long blockBase = (long)b * THR * IT;

    // ---- phase 0: fire-and-forget cp.async for cut + AB (ready tables) ----
    {
        unsigned cut_s = (unsigned)__cvta_generic_to_shared(scut);
        unsigned ab_s  = (unsigned)__cvta_generic_to_shared(sAB);
        const char* cut_g = (const char*)g_cutC;
        const char* ab_g  = (const char*)g_ABC;
        #pragma unroll 1
        for (int i = t; i < NCMAX / 4; i += THR)               // 4160 chunks
            asm volatile("cp.async.cg.shared.global [%0], [%1], 16;"
                         :: "r"(cut_s + i * 16), "l"(cut_g + i * 16));
        #pragma unroll 1
        for (int i = t; i < ((NPMAX + 1) * 8) / 16; i += THR)  // 8321 chunks
            asm volatile("cp.async.cg.shared.global [%0], [%1], 16;"
                         :: "r"(ab_s + i * 16), "l"(ab_g + i * 16));
        asm volatile("cp.async.commit_group;");
    }

    // ---- phase A: scan (hoisted x loads, ballot cummax) ----
    float xr[IT];
    int   vloc[IT];
    int   rr[IT];
    int cntLoc = 0;
    #pragma unroll
    for (int tile = 0; tile < IT; tile++) {
        long row = blockBase + (long)tile * THR + t;
        xr[tile] = (row < N) ? __ldg(x + row) : 0.0f;
    }
    #pragma unroll
    for (int tile = 0; tile < IT; tile++) {
        long row = blockBase + (long)tile * THR + t;
        bool valid = row < N;
        float cur = xr[tile];
        float pv = __shfl_up_sync(0xffffffffu, cur, 1);
        if (lane == 0) pv = (valid && row > 0) ? __ldg(x + row - 1) : cur;
        bool m = valid && ((row == 0) || fabsf(cur - pv) > THRESH);
        unsigned bits = __ballot_sync(0xffffffffu, m);
        cntLoc += m ? 1 : 0;
        int warpBase = (int)row - lane;
        unsigned below = bits & (0xffffffffu >> (31 - lane));
        vloc[tile] = below ? (warpBase + 31 - __clz(below)) : -1;
        if (lane == 31) stot[tile * NWARP + w] = bits ? (warpBase + 31 - __clz(bits)) : -1;
    }
    __syncthreads();
    if (w == 0) {
        int vals[IT];
        int running = -1;
        #pragma unroll
        for (int i = 0; i < IT; i++) {
            int u = stot[lane * IT + i];
            vals[i] = running;
            running = max(running, u);
        }
        int inc = running;
        #pragma unroll
        for (int o = 1; o < 32; o <<= 1) {
            int u = __shfl_up_sync(0xffffffffu, inc, o);
            if (lane >= o) inc = max(inc, u);
        }
        int exc = __shfl_up_sync(0xffffffffu, inc, 1);
        if (lane == 0) exc = -1;
        #pragma unroll
        for (int i = 0; i < IT; i++) stot[lane * IT + i] = max(vals[i], exc);
        if (lane == 31) sBlockLast = inc;
    }
    __syncthreads();
    #pragma unroll
    for (int tile = 0; tile < IT; tile++)
        rr[tile] = max(vloc[tile], stot[tile * NWARP + w]);
    int carry = sBlockLast;

    // ---- publish packet ----
    {
        int c = cntLoc;
        #pragma unroll
        for (int o = 16; o; o >>= 1) c += __shfl_xor_sync(0xffffffffu, c, o);
        if (lane == 0) swarp[w] = c;
        __syncthreads();
        if (t == 0) {
            int s = 0;
            #pragma unroll
            for (int i = 0; i < NWARP; i++) s += swarp[i];
            sCntOwn = s;
            unsigned long long pack =
                ((unsigned long long)(unsigned)(carry + 2) << 32) | (unsigned)s;
            atomicExch(&g_sync[b], pack);
        }
        __syncthreads();
    }

    // ---- decoupled lookback (seed only) ----
    {
        int lastMax = -1;
        for (int i = t; i < b; i += THR) {
            volatile unsigned long long* p = (volatile unsigned long long*)(g_sync + i);
            unsigned long long v;
            do { v = *p; } while (v == 0ull);
            lastMax = max(lastMax, (int)(unsigned)(v >> 32) - 2);
        }
        #pragma unroll
        for (int o = 16; o; o >>= 1)
            lastMax = max(lastMax, __shfl_xor_sync(0xffffffffu, lastMax, o));
        if (lane == 0) swarp[w] = lastMax;
        __syncthreads();
        if (t == 0) {
            int mx = -1;
            #pragma unroll
            for (int i = 0; i < NWARP; i++) mx = max(mx, swarp[i]);
            sSeedSh = mx;
        }
        if (b == 0)
            for (int i = N + 1 + t; i < out_size; i += THR) out[i] = 0.0f;
    }

    // ---- wait bins flag, copy sbin; wait cp.async; INF-pad cuts ----
    if (t == 0) { while (g_flag == 0u) { } }
    __syncthreads();
    __threadfence();
    {
        const int4* bg = (const int4*)g_bin;
        int4* bs = (int4*)sbin;
        for (int i = t; i < BIN_BYTES / 16; i += THR) bs[i] = bg[i];
    }
    asm volatile("cp.async.wait_group 0;");
    __syncthreads();
    int NC = g_meta[0];
    if (t < 12) scut[NC + t] = CUDART_INF_F;
    __syncthreads();
    int seed = sSeedSh;

    // ---- eval: bin -> window -> vector count (independent LDS.128) ----
    const float4* scut4 = (const float4*)scut;
    #pragma unroll
    for (int tile = 0; tile < IT; tile++) {
        long row = blockBase + (long)tile * THR + t;
        if (row >= N) break;
        int irow = (int)row;
        int run = max(rr[tile], seed);
        bool own = (run == irow);
        float xv = own ? xr[tile] : __ldg(x + run);
        int bin = (int)((xv - XLO) * BINSCALE);
        bin = min(max(bin, 0), NB - 1);
        int lo = sbin[bin], hi = sbin[bin + 1];
        int piece;
        int qb = lo >> 2;
        int i0 = qb << 2;
        if (hi <= i0 + 12) {
            float4 c0 = scut4[qb];
            float4 c1 = scut4[qb + 1];
            float4 c2 = scut4[qb + 2];
            float vv[12] = {c0.x, c0.y, c0.z, c0.w, c1.x, c1.y, c1.z, c1.w,
                            c2.x, c2.y, c2.z, c2.w};
            int cnt = 0;
            #pragma unroll
            for (int k = 0; k < 12; k++) {
                int idx = i0 + k;
                cnt += (idx >= lo && idx < hi && vv[k] < xv) ? 1 : 0;
            }
            piece = lo + cnt;
        } else {
            while (lo < hi) {
                int mid = (lo + hi) >> 1;
                if (scut[mid] < xv) lo = mid + 1; else hi = mid;
            }
            piece = lo;
        }
        float2 ab = sAB[piece];
        float y = fmaf(ab.x, xv, ab.y);
        if (!own) y *= __expf((float)(run - irow) * INV_TAU);
        out[row] = y;
    }
}

#define LAUNCH_MAIN(ITV)                                                        \
    do {                                                                        \
        cudaFuncSetAttribute(k_main<ITV>,                                       \
            cudaFuncAttributeMaxDynamicSharedMemorySize, (int)SMEM_MAIN);       \
        k_main<ITV><<<grid1, THR, SMEM_MAIN>>>(x, out, N, out_size);            \
    } while (0)

extern "C" void kernel_launch(void* const* d_in, const int* in_sizes, int n_in,
                              void* d_out, int out_size) {
    const float* x  = (const float*)d_in[0];
    const float* W1 = (const float*)d_in[1];
    const float* b1 = (const float*)d_in[2];
    const float* W2 = (const float*)d_in[3];
    const float* b2 = (const float*)d_in[4];
    const float* W3 = (const float*)d_in[5];
    const float* b3 = (const float*)d_in[6];
    float* out = (float*)d_out;
    int N = in_sizes[0];

    size_t smemA = (size_t)H * HP * sizeof(float);
    cudaFuncSetAttribute(k_build, cudaFuncAttributeMaxDynamicSharedMemorySize, (int)smemA);
    k_build<<<NSEG, BT, smemA>>>(W1, b1, W2, b2, W3, b3);

    const int SMS = 147;   // scanners; +1 bins block = 148 <= SM count
    long total = N;
    int IT = (int)((total + (long)SMS * THR - 1) / ((long)SMS * THR));
    if (IT < 1) IT = 1;
    if (IT > 16) IT = 16;
    int SCANB = (int)((total + (long)THR * IT - 1) / ((long)THR * IT));
    if (SCANB < 1) SCANB = 1;
    int grid1 = SCANB + 1;

    switch (IT) {
        case 1:  LAUNCH_MAIN(1);  break;
        case 2:  LAUNCH_MAIN(2);  break;
        case 3:  LAUNCH_MAIN(3);  break;
        case 4:  LAUNCH_MAIN(4);  break;
        case 5:  LAUNCH_MAIN(5);  break;
        case 6:  LAUNCH_MAIN(6);  break;
        case 7:  LAUNCH_MAIN(7);  break;
        case 8:  LAUNCH_MAIN(8);  break;
        case 9:  LAUNCH_MAIN(9);  break;
        case 10: LAUNCH_MAIN(10); break;
        case 11: LAUNCH_MAIN(11); break;
        case 12: LAUNCH_MAIN(12); break;
        case 13: LAUNCH_MAIN(13); break;
        case 14: LAUNCH_MAIN(14); break;
        case 15: LAUNCH_MAIN(15); break;
        default: LAUNCH_MAIN(16); break;
    }
}